// round 7
// baseline (speedup 1.0000x reference)
#include <cuda_runtime.h>

#define THETA 0.9999f

// Exact IF-neuron spike-rate over 50 steps with constant drive a (soft reset).
// Closed form floor(50*a/theta); exact f32 sim only within 1e-4 of a boundary.
__device__ __forceinline__ float rate50(float a) {
    if (a <= 0.0f) return 0.0f;
    if (a >= THETA) return 1.0f;
    float u = a * (50.0f / THETA);
    float k = floorf(u);
    float d = u - k;
    if (d > 1e-4f && d < 0.9999f) {
        return k * 0.02f;
    }
    float v = 0.0f, cnt = 0.0f;
    #pragma unroll
    for (int t = 0; t < 50; ++t) {
        v += a;
        if (v >= THETA) { v -= THETA; cnt += 1.0f; }
    }
    return cnt * 0.02f;
}

// Shared layout (floats):
//   A [0,184)    : mx (data at h+1, pads zero); later 32 reduction partials
//   B [184,3256) : r1 (16 rows stride 184, data at h+1) then r3 (32 rows stride 96, data at h+1)
//   C [3256,8888): r2 (32 rows stride 176) then r4 (32 rows stride 88)
#define SM_TOTAL 8888
#define B_OFF 184
#define C_OFF 3256

// Generic sliding-window conv + rate over a contiguous h-range.
// Output h index = h0+j; reads input rows at [h0+j .. h0+j+K-1] (data-at-+1 handles pad-1).
template<int CHUNK, int K>
__device__ __forceinline__ void conv_stage(
    const float* __restrict__ Bsh, float* __restrict__ Csh,
    const float* __restrict__ w, const float* __restrict__ b,
    int nch, int in_stride, int out_stride,
    int lo, int hi, int tid)
{
    int o = tid >> 3;
    int s = tid & 7;
    int h0 = lo + s * CHUNK;
    float acc[CHUNK];
    float bb = b[o];
    #pragma unroll
    for (int j = 0; j < CHUNK; ++j) acc[j] = bb;
    for (int c = 0; c < nch; ++c) {
        float win[CHUNK + K - 1];
        const float* row = Bsh + c * in_stride + h0;
        #pragma unroll
        for (int j = 0; j < CHUNK + K - 1; ++j) win[j] = row[j];
        const float* wp = w + (o * nch + c) * K;
        #pragma unroll
        for (int k = 0; k < K; ++k) {
            float wv = wp[k];
            #pragma unroll
            for (int j = 0; j < CHUNK; ++j) acc[j] += win[j + k] * wv;
        }
    }
    #pragma unroll
    for (int j = 0; j < CHUNK; ++j)
        if (h0 + j < hi) Csh[o * out_stride + h0 + j] = rate50(acc[j]);
}

__global__ void zero_out_kernel(float* __restrict__ out, int n) {
    int i = blockIdx.x * blockDim.x + threadIdx.x;
    if (i < n) out[i] = 0.0f;
}

__global__ __launch_bounds__(256, 4)
void catnet_kernel(const float* __restrict__ x,
                   const float* __restrict__ w1, const float* __restrict__ b1,
                   const float* __restrict__ w2, const float* __restrict__ b2,
                   const float* __restrict__ w3, const float* __restrict__ b3,
                   const float* __restrict__ wf, const float* __restrict__ bf,
                   float* __restrict__ out) {
    __shared__ float sm[SM_TOTAL];
    float* A = sm;
    float* B = sm + B_OFF;
    float* C = sm + C_OFF;
    const int tid = threadIdx.x;
    const int n = blockIdx.x >> 1;
    const int half = blockIdx.x & 1;

    // zero all shared (establishes every pad cell)
    for (int i = tid; i < SM_TOTAL; i += 256) sm[i] = 0.0f;
    __syncthreads();

    // per-half stage ranges (global h)
    const int mx_lo  = half ? 84 : 0,  mx_w  = half ? 96  : 106;
    const int r1_lo  = half ? 85 : 0,  r1_w  = half ? 95  : 105;

    // ---- stage 0: mean over time -> A[h+1] for h in [mx_lo, mx_lo+mx_w) ----
    const float2* xn2 = (const float2*)(x + (long)n * (180 * 50));
    if (tid < mx_w) {
        int h = mx_lo + tid;
        const float2* xp = xn2 + h * 25;
        float s0 = 0.0f, s1 = 0.0f;
        #pragma unroll
        for (int t = 0; t < 25; ++t) {
            float2 v = xp[t];
            s0 += v.x; s1 += v.y;
        }
        A[h + 1] = (s0 + s1) / 50.0f;
    }
    __syncthreads();

    // ---- stage 1: conv (16,1,3) pad 1 + rate -> r1 in B ----
    for (int idx = tid; idx < 16 * r1_w; idx += 256) {
        int o = idx / r1_w, h = r1_lo + idx - o * r1_w;
        float a = b1[o]
                + A[h]     * w1[o * 3]
                + A[h + 1] * w1[o * 3 + 1]
                + A[h + 2] * w1[o * 3 + 2];
        B[o * 184 + h + 1] = rate50(a);
    }
    __syncthreads();

    // ---- stage 2: conv (32,16,9) pad 1 + rate -> r2 in C ----
    if (half == 0)
        conv_stage<13, 9>(B, C, w2, b2, 16, 184, 176, 0, 98, tid);
    else
        conv_stage<11, 9>(B, C, w2, b2, 16, 184, 176, 86, 174, tid);
    __syncthreads();

    // ---- stage 3: sum-pool(2)*1.1 + rate -> r3 in B (stride 96, data at h+1) ----
    {
        const int r3_lo = half ? 43 : 0;
        const int r3_w  = half ? 44 : 49;
        for (int idx = tid; idx < 32 * r3_w; idx += 256) {
            int o = idx / r3_w, h = r3_lo + idx - o * r3_w;
            float a = 1.1f * (C[o * 176 + 2 * h] + C[o * 176 + 2 * h + 1]);
            B[o * 96 + h + 1] = rate50(a);
        }
    }
    // zero r3 pad cells (B previously held r1) + reduction scratch
    if (tid < 32) {
        B[tid * 96] = 0.0f;
        #pragma unroll
        for (int j = 88; j < 96; ++j) B[tid * 96 + j] = 0.0f;
        A[tid] = 0.0f;
    }
    __syncthreads();

    // ---- stage 4: conv (32,32,7) pad 1 + rate -> r4 in C (stride 88) ----
    if (half == 0)
        conv_stage<6, 7>(B, C, w3, b3, 32, 96, 88, 0, 44, tid);
    else
        conv_stage<6, 7>(B, C, w3, b3, 32, 96, 88, 44, 83, tid);
    __syncthreads();

    // ---- stage 5: dense partial over this half's r4 h-range ----
    {
        const int d_lo = half ? 44 : 0;
        const int d_w  = half ? 39 : 44;
        float p0 = 0.f, p1 = 0.f, p2 = 0.f, p3 = 0.f;
        for (int idx = tid; idx < 32 * d_w; idx += 256) {
            int c = idx / d_w, h = d_lo + idx - c * d_w;
            float v = C[c * 88 + h];
            int wi = c * 83 + h;
            p0 += v * wf[wi];
            p1 += v * wf[wi + 2656];
            p2 += v * wf[wi + 2 * 2656];
            p3 += v * wf[wi + 3 * 2656];
        }
        #pragma unroll
        for (int off = 16; off; off >>= 1) {
            p0 += __shfl_down_sync(0xffffffffu, p0, off);
            p1 += __shfl_down_sync(0xffffffffu, p1, off);
            p2 += __shfl_down_sync(0xffffffffu, p2, off);
            p3 += __shfl_down_sync(0xffffffffu, p3, off);
        }
        int lane = tid & 31, wid = tid >> 5;
        if (lane == 0) {
            A[wid * 4 + 0] = p0;
            A[wid * 4 + 1] = p1;
            A[wid * 4 + 2] = p2;
            A[wid * 4 + 3] = p3;
        }
    }
    __syncthreads();
    if (tid < 4) {
        float s = (half == 0) ? bf[tid] : 0.0f;   // bias added exactly once
        #pragma unroll
        for (int w = 0; w < 8; ++w) s += A[w * 4 + tid];
        atomicAdd(&out[n * 4 + tid], s);          // 2 commutative adds -> deterministic
    }
}

extern "C" void kernel_launch(void* const* d_in, const int* in_sizes, int n_in,
                              void* d_out, int out_size) {
    const float* x  = (const float*)d_in[0];
    const float* w1 = (const float*)d_in[1];
    const float* b1 = (const float*)d_in[2];
    const float* w2 = (const float*)d_in[3];
    const float* b2 = (const float*)d_in[4];
    const float* w3 = (const float*)d_in[5];
    const float* b3 = (const float*)d_in[6];
    const float* wf = (const float*)d_in[7];
    const float* bf = (const float*)d_in[8];
    float* out = (float*)d_out;

    int n = in_sizes[0] / (180 * 50);   // batch size (256)
    zero_out_kernel<<<(out_size + 255) / 256, 256>>>(out, out_size);
    catnet_kernel<<<2 * n, 256>>>(x, w1, b1, w2, b2, w3, b3, wf, bf, out);
}

// round 8
// speedup vs baseline: 1.3068x; 1.3068x over previous
#include <cuda_runtime.h>

#define THETA 0.9999f
typedef unsigned long long ull;

__device__ __forceinline__ ull pk2(float x, float y) {
    ull r; asm("mov.b64 %0, {%1, %2};" : "=l"(r) : "f"(x), "f"(y)); return r;
}
__device__ __forceinline__ void upk2(float& x, float& y, ull v) {
    asm("mov.b64 {%0, %1}, %2;" : "=f"(x), "=f"(y) : "l"(v));
}
__device__ __forceinline__ ull fma2(ull a, ull b, ull c) {
    ull d; asm("fma.rn.f32x2 %0, %1, %2, %3;" : "=l"(d) : "l"(a), "l"(b), "l"(c)); return d;
}

// IF-neuron spike rate over 50 steps, constant drive a, soft reset.
// Closed form floor(50*a/theta); exact f32 sim near boundaries.
__device__ __forceinline__ float rate50(float a) {
    if (a <= 0.0f) return 0.0f;
    if (a >= THETA) return 1.0f;
    float u = a * (50.0f / THETA);
    float k = floorf(u);
    float d = u - k;
    if (d > 1e-4f && d < 0.9999f) {
        return k * 0.02f;
    }
    float v = 0.0f, cnt = 0.0f;
    #pragma unroll
    for (int t = 0; t < 50; ++t) {
        v += a;
        if (v >= THETA) { v -= THETA; cnt += 1.0f; }
    }
    return cnt * 0.02f;
}

// Shared layout (floats):
//   A [0,184)    : mx (data at h+1, pads zero); later 32 reduction partials
//   B [184,3256) : r1 (16 rows stride 184, data at h+1) then r3 (32 rows stride 96, data at h+1)
//   C [3256,8888): r2 (32 rows stride 176) then r4 (32 rows stride 88)
#define SM_TOTAL 8888
#define B_OFF 184
#define C_OFF 3256

__global__ __launch_bounds__(256, 2)
void catnet_kernel(const float* __restrict__ x,
                   const float* __restrict__ w1, const float* __restrict__ b1,
                   const float* __restrict__ w2, const float* __restrict__ b2,
                   const float* __restrict__ w3, const float* __restrict__ b3,
                   const float* __restrict__ wf, const float* __restrict__ bf,
                   float* __restrict__ out) {
    __shared__ float sm[SM_TOTAL];
    float* A = sm;
    float* B = sm + B_OFF;
    float* C = sm + C_OFF;
    const int tid = threadIdx.x;
    const int n = blockIdx.x;

    for (int i = tid; i < SM_TOTAL; i += 256) sm[i] = 0.0f;
    __syncthreads();

    // ---- stage 0: mean over time -> A[h+1] ----
    const float2* xn2 = (const float2*)(x + (long)n * (180 * 50));
    for (int h = tid; h < 180; h += 256) {
        const float2* xp = xn2 + h * 25;
        float s0 = 0.0f, s1 = 0.0f;
        #pragma unroll
        for (int t = 0; t < 25; ++t) {
            float2 v = xp[t];
            s0 += v.x; s1 += v.y;
        }
        A[h + 1] = (s0 + s1) / 50.0f;
    }
    __syncthreads();

    // ---- stage 1: conv (16,1,3) pad 1 + rate -> r1 in B (stride 184, data at h+1) ----
    for (int idx = tid; idx < 16 * 180; idx += 256) {
        int o = idx / 180, h = idx - o * 180;
        float a = b1[o]
                + A[h]     * w1[o * 3]
                + A[h + 1] * w1[o * 3 + 1]
                + A[h + 2] * w1[o * 3 + 2];
        B[o * 184 + h + 1] = rate50(a);
    }
    __syncthreads();

    // ---- stage 2: conv (32,16,9) pad 1 + rate -> r2 in C (stride 176) ----
    // Packed f32x2: even taps -> accE (pairs (0,1),(2,3),..), odd taps -> accO
    // (pairs (1,2),(3,4),..); odd-tap start for odd-paired outputs is even ->
    // all window operands are aligned LDS.64 pairs. Output 0's odd taps scalar.
    {
        int o = tid >> 3;
        int h0 = (tid & 7) * 24;            // even -> 8B-aligned windows
        float bb = b2[o];
        ull bb2 = pk2(bb, bb);
        ull accE[12], accO[12];
        #pragma unroll
        for (int m = 0; m < 12; ++m) { accE[m] = bb2; accO[m] = 0ULL; }
        float acc0o = 0.0f;
        for (int c = 0; c < 16; ++c) {
            const float* row = B + c * 184 + h0;
            const ull* row2 = (const ull*)row;
            ull E[16];
            #pragma unroll
            for (int m = 0; m < 16; ++m) E[m] = row2[m];   // win[0..31]
            const float* wp = w2 + (o * 16 + c) * 9;
            #pragma unroll
            for (int k = 0; k < 9; k += 2) {               // even taps
                float wv = wp[k];
                ull wv2 = pk2(wv, wv);
                int b0 = k >> 1;
                #pragma unroll
                for (int m = 0; m < 12; ++m) accE[m] = fma2(E[m + b0], wv2, accE[m]);
            }
            #pragma unroll
            for (int k = 1; k < 9; k += 2) {               // odd taps
                float wv = wp[k];
                ull wv2 = pk2(wv, wv);
                int b0 = (k + 1) >> 1;
                #pragma unroll
                for (int m = 0; m < 12; ++m) accO[m] = fma2(E[m + b0], wv2, accO[m]);
                acc0o += row[k] * wv;                      // output j=0, odd taps
            }
        }
        float accs[24], od[25];
        od[0] = acc0o;
        #pragma unroll
        for (int m = 0; m < 12; ++m) {
            float e0, e1; upk2(e0, e1, accE[m]);
            accs[2 * m] = e0; accs[2 * m + 1] = e1;
            float o0, o1; upk2(o0, o1, accO[m]);
            od[2 * m + 1] = o0; od[2 * m + 2] = o1;
        }
        #pragma unroll
        for (int j = 0; j < 24; ++j) {
            int h = h0 + j;
            if (h < 174) C[o * 176 + h] = rate50(accs[j] + od[j]);
        }
    }
    __syncthreads();

    // ---- stage 3: sum-pool(2)*1.1 + rate -> r3 in B (stride 96, data at h+1) ----
    for (int idx = tid; idx < 32 * 87; idx += 256) {
        int o = idx / 87, h = idx - o * 87;
        float a = 1.1f * (C[o * 176 + 2 * h] + C[o * 176 + 2 * h + 1]);
        B[o * 96 + h + 1] = rate50(a);
    }
    // zero r3 pad cells (B previously held r1) + reduction scratch
    if (tid < 32) {
        B[tid * 96] = 0.0f;
        #pragma unroll
        for (int j = 88; j < 96; ++j) B[tid * 96 + j] = 0.0f;
        A[tid] = 0.0f;
    }
    __syncthreads();

    // ---- stage 4: conv (32,32,7) pad 1 + rate -> r4 in C (stride 88) ----
    {
        int o = tid >> 3;
        int h0 = (tid & 7) * 12;            // even -> aligned
        float bb = b3[o];
        ull bb2 = pk2(bb, bb);
        ull accE[6], accO[6];
        #pragma unroll
        for (int m = 0; m < 6; ++m) { accE[m] = bb2; accO[m] = 0ULL; }
        float acc0o = 0.0f;
        for (int c = 0; c < 32; ++c) {
            const float* row = B + c * 96 + h0;
            const ull* row2 = (const ull*)row;
            ull E[9];
            #pragma unroll
            for (int m = 0; m < 9; ++m) E[m] = row2[m];    // win[0..17]
            const float* wp = w3 + (o * 32 + c) * 7;
            #pragma unroll
            for (int k = 0; k < 7; k += 2) {               // even taps
                float wv = wp[k];
                ull wv2 = pk2(wv, wv);
                int b0 = k >> 1;
                #pragma unroll
                for (int m = 0; m < 6; ++m) accE[m] = fma2(E[m + b0], wv2, accE[m]);
            }
            #pragma unroll
            for (int k = 1; k < 7; k += 2) {               // odd taps
                float wv = wp[k];
                ull wv2 = pk2(wv, wv);
                int b0 = (k + 1) >> 1;
                #pragma unroll
                for (int m = 0; m < 6; ++m) accO[m] = fma2(E[m + b0], wv2, accO[m]);
                acc0o += row[k] * wv;
            }
        }
        float accs[12], od[13];
        od[0] = acc0o;
        #pragma unroll
        for (int m = 0; m < 6; ++m) {
            float e0, e1; upk2(e0, e1, accE[m]);
            accs[2 * m] = e0; accs[2 * m + 1] = e1;
            float o0, o1; upk2(o0, o1, accO[m]);
            od[2 * m + 1] = o0; od[2 * m + 2] = o1;
        }
        #pragma unroll
        for (int j = 0; j < 12; ++j) {
            int h = h0 + j;
            if (h < 83) C[o * 88 + h] = rate50(accs[j] + od[j]);
        }
    }
    __syncthreads();

    // ---- stage 5: dense out[n,o] = sum_{c,h} r4[c,h]*wf[o,c,h] + bf[o] ----
    {
        float p0 = 0.f, p1 = 0.f, p2 = 0.f, p3 = 0.f;
        for (int idx = tid; idx < 32 * 83; idx += 256) {
            int c = idx / 83, h = idx - c * 83;
            float v = C[c * 88 + h];
            int wi = c * 83 + h;
            p0 += v * wf[wi];
            p1 += v * wf[wi + 2656];
            p2 += v * wf[wi + 2 * 2656];
            p3 += v * wf[wi + 3 * 2656];
        }
        #pragma unroll
        for (int off = 16; off; off >>= 1) {
            p0 += __shfl_down_sync(0xffffffffu, p0, off);
            p1 += __shfl_down_sync(0xffffffffu, p1, off);
            p2 += __shfl_down_sync(0xffffffffu, p2, off);
            p3 += __shfl_down_sync(0xffffffffu, p3, off);
        }
        int lane = tid & 31, wid = tid >> 5;
        if (lane == 0) {
            A[wid * 4 + 0] = p0;
            A[wid * 4 + 1] = p1;
            A[wid * 4 + 2] = p2;
            A[wid * 4 + 3] = p3;
        }
    }
    __syncthreads();
    if (tid < 4) {
        float s = bf[tid];
        #pragma unroll
        for (int w = 0; w < 8; ++w) s += A[w * 4 + tid];
        out[n * 4 + tid] = s;
    }
}

extern "C" void kernel_launch(void* const* d_in, const int* in_sizes, int n_in,
                              void* d_out, int out_size) {
    const float* x  = (const float*)d_in[0];
    const float* w1 = (const float*)d_in[1];
    const float* b1 = (const float*)d_in[2];
    const float* w2 = (const float*)d_in[3];
    const float* b2 = (const float*)d_in[4];
    const float* w3 = (const float*)d_in[5];
    const float* b3 = (const float*)d_in[6];
    const float* wf = (const float*)d_in[7];
    const float* bf = (const float*)d_in[8];
    float* out = (float*)d_out;

    int n = in_sizes[0] / (180 * 50);   // batch size (256)
    catnet_kernel<<<n, 256>>>(x, w1, b1, w2, b2, w3, b3, wf, bf, out);
}